// round 2
// baseline (speedup 1.0000x reference)
#include <cuda_runtime.h>
#include <cstdint>

// BatchedHGNNLayer: out = diag(Dv^-1/2) H diag(De^-1) H^T diag(Dv^-1/2) x W^T + b
// B=8, N=4096, E=2048, C=128 (fp32)

#define B_ 8
#define N_ 4096
#define E_ 2048
#define C_ 128
#define EPS 1e-6f

// ---------------- scratch (device globals; no cudaMalloc allowed) ----------
__device__ float g_DvInv[B_ * N_];          // rsqrt(node degree)
__device__ float g_DeP[8][B_ * E_];         // partial column sums (deterministic 2-stage)
__device__ float g_De[B_ * E_];             // edge degree (+eps)
__device__ float g_M[B_ * E_ * C_];         // intermediate  De^-1 H^T Xs
__device__ float g_Y[(size_t)B_ * N_ * C_]; // intermediate  H M * DvInv
__device__ float g_Wt[C_ * C_];             // W^T

// ---------------- degree kernels -------------------------------------------
__global__ void dv_kernel(const float* __restrict__ Hg) {
    // one warp per row; blockDim (32,8); grid B_*N_/8
    int row = blockIdx.x * 8 + threadIdx.y;
    const float4* h4 = (const float4*)(Hg + (size_t)row * E_);
    float s = 0.f;
    for (int i = threadIdx.x; i < E_ / 4; i += 32) {
        float4 v = h4[i];
        s += (v.x + v.y) + (v.z + v.w);
    }
    #pragma unroll
    for (int o = 16; o; o >>= 1) s += __shfl_xor_sync(0xffffffffu, s, o);
    if (threadIdx.x == 0) g_DvInv[row] = rsqrtf(s + EPS);
}

__global__ void de_part_kernel(const float* __restrict__ Hg) {
    // grid (E_/128, 8 splits, B_), block 128
    int e = blockIdx.x * 128 + threadIdx.x;
    int b = blockIdx.z;
    int s = blockIdx.y;
    const float* p = Hg + ((size_t)b * N_ + (size_t)s * 512) * E_ + e;
    float a0 = 0.f, a1 = 0.f, a2 = 0.f, a3 = 0.f;
    #pragma unroll 4
    for (int n = 0; n < 512; n += 4) {
        a0 += p[(size_t)(n + 0) * E_];
        a1 += p[(size_t)(n + 1) * E_];
        a2 += p[(size_t)(n + 2) * E_];
        a3 += p[(size_t)(n + 3) * E_];
    }
    g_DeP[s][b * E_ + e] = (a0 + a1) + (a2 + a3);
}

__global__ void de_reduce_kernel() {
    int i = blockIdx.x * 256 + threadIdx.x;   // B_*E_ = 16384 threads
    float s = EPS;
    #pragma unroll
    for (int k = 0; k < 8; k++) s += g_DeP[k][i];
    g_De[i] = s;
}

__global__ void wt_kernel(const float* __restrict__ W) {
    int idx = blockIdx.x * 256 + threadIdx.x; // 16384
    int j = idx >> 7, k = idx & 127;
    g_Wt[k * C_ + j] = W[idx];
}

// ---------------- GEMM1: M[b,e,c] = (1/De) * sum_n H[b,n,e] * x[b,n,c]*DvInv[b,n]
// A = H^T tile loads are naturally k-major/contiguous. BM=128(e) BN=128(c) BK=16.
__global__ __launch_bounds__(256) void gemm1_kernel(const float* __restrict__ Hg,
                                                    const float* __restrict__ xg) {
    const int b  = blockIdx.z;
    const int e0 = blockIdx.x * 128;
    const float* Hb = Hg + (size_t)b * N_ * E_;
    const float* xb = xg + (size_t)b * N_ * C_;
    const float* dv = g_DvInv + b * N_;

    __shared__ float As[2][16][132];
    __shared__ float Bs[2][16][128];

    const int tid = threadIdx.x;
    const int tx = tid & 15, ty = tid >> 4;

    float acc[8][8];
    #pragma unroll
    for (int i = 0; i < 8; i++)
        #pragma unroll
        for (int j = 0; j < 8; j++) acc[i][j] = 0.f;

    float4 ra[2], rb[2];

    #define G1_LOAD(n0)                                                        \
        _Pragma("unroll")                                                      \
        for (int i = 0; i < 2; i++) {                                          \
            int f = tid + i * 256;                                             \
            int k = f >> 5, q = f & 31;                                        \
            ra[i] = *(const float4*)(Hb + (size_t)((n0) + k) * E_ + e0 + q*4); \
            float s = dv[(n0) + k];                                            \
            float4 v = *(const float4*)(xb + (size_t)((n0) + k) * C_ + q*4);   \
            v.x *= s; v.y *= s; v.z *= s; v.w *= s;                            \
            rb[i] = v;                                                         \
        }
    #define G1_STORE(buf)                                                      \
        _Pragma("unroll")                                                      \
        for (int i = 0; i < 2; i++) {                                          \
            int f = tid + i * 256;                                             \
            int k = f >> 5, q = f & 31;                                        \
            *(float4*)&As[buf][k][q * 4] = ra[i];                              \
            *(float4*)&Bs[buf][k][q * 4] = rb[i];                              \
        }

    G1_LOAD(0); G1_STORE(0); __syncthreads();
    const int KT = N_ / 16;
    for (int kt = 0; kt < KT; ++kt) {
        int cur = kt & 1;
        if (kt + 1 < KT) { G1_LOAD((kt + 1) * 16); }
        #pragma unroll
        for (int kk = 0; kk < 16; kk++) {
            float a[8], bb[8];
            *(float4*)&a[0]  = *(const float4*)&As[cur][kk][ty * 4];
            *(float4*)&a[4]  = *(const float4*)&As[cur][kk][64 + ty * 4];
            *(float4*)&bb[0] = *(const float4*)&Bs[cur][kk][tx * 4];
            *(float4*)&bb[4] = *(const float4*)&Bs[cur][kk][64 + tx * 4];
            #pragma unroll
            for (int i = 0; i < 8; i++)
                #pragma unroll
                for (int j = 0; j < 8; j++) acc[i][j] += a[i] * bb[j];
        }
        if (kt + 1 < KT) { G1_STORE(cur ^ 1); }
        __syncthreads();
    }

    float* Mb = g_M + (size_t)b * E_ * C_;
    #pragma unroll
    for (int i = 0; i < 8; i++) {
        int e = e0 + ((i < 4) ? (ty * 4 + i) : (64 + ty * 4 + (i - 4)));
        float s = 1.0f / g_De[b * E_ + e];
        float4 v0 = make_float4(acc[i][0]*s, acc[i][1]*s, acc[i][2]*s, acc[i][3]*s);
        float4 v1 = make_float4(acc[i][4]*s, acc[i][5]*s, acc[i][6]*s, acc[i][7]*s);
        *(float4*)(Mb + (size_t)e * C_ + tx * 4)      = v0;
        *(float4*)(Mb + (size_t)e * C_ + 64 + tx * 4) = v1;
    }
}

// ---------------- GEMM2: Y[b,n,c] = DvInv[b,n] * sum_e H[b,n,e] * M[b,e,c]
// A = H, normal layout -> transpose-on-load into As[k][m].
__global__ __launch_bounds__(256) void gemm2_kernel(const float* __restrict__ Hg) {
    const int b  = blockIdx.z;
    const int n0 = blockIdx.x * 128;
    const float* Hb = Hg + (size_t)b * N_ * E_;
    const float* Mb = g_M + (size_t)b * E_ * C_;
    const float* dv = g_DvInv + b * N_;

    __shared__ float As[2][16][132];
    __shared__ float Bs[2][16][128];

    const int tid = threadIdx.x;
    const int tx = tid & 15, ty = tid >> 4;

    float acc[8][8];
    #pragma unroll
    for (int i = 0; i < 8; i++)
        #pragma unroll
        for (int j = 0; j < 8; j++) acc[i][j] = 0.f;

    float4 ra[2], rb[2];

    #define G2_LOAD(k0)                                                        \
        _Pragma("unroll")                                                      \
        for (int i = 0; i < 2; i++) {                                          \
            int f = tid + i * 256;                                             \
            int m = f >> 2, q = f & 3;                                         \
            ra[i] = *(const float4*)(Hb + (size_t)(n0 + m) * E_ + (k0) + q*4); \
            int k = f >> 5, c = f & 31;                                        \
            rb[i] = *(const float4*)(Mb + (size_t)((k0) + k) * C_ + c * 4);    \
        }
    #define G2_STORE(buf)                                                      \
        _Pragma("unroll")                                                      \
        for (int i = 0; i < 2; i++) {                                          \
            int f = tid + i * 256;                                             \
            int m = f >> 2, q = f & 3;                                         \
            As[buf][q * 4 + 0][m] = ra[i].x;                                   \
            As[buf][q * 4 + 1][m] = ra[i].y;                                   \
            As[buf][q * 4 + 2][m] = ra[i].z;                                   \
            As[buf][q * 4 + 3][m] = ra[i].w;                                   \
            int k = f >> 5, c = f & 31;                                        \
            *(float4*)&Bs[buf][k][c * 4] = rb[i];                              \
        }

    G2_LOAD(0); G2_STORE(0); __syncthreads();
    const int KT = E_ / 16;
    for (int kt = 0; kt < KT; ++kt) {
        int cur = kt & 1;
        if (kt + 1 < KT) { G2_LOAD((kt + 1) * 16); }
        #pragma unroll
        for (int kk = 0; kk < 16; kk++) {
            float a[8], bb[8];
            *(float4*)&a[0]  = *(const float4*)&As[cur][kk][ty * 4];
            *(float4*)&a[4]  = *(const float4*)&As[cur][kk][64 + ty * 4];
            *(float4*)&bb[0] = *(const float4*)&Bs[cur][kk][tx * 4];
            *(float4*)&bb[4] = *(const float4*)&Bs[cur][kk][64 + tx * 4];
            #pragma unroll
            for (int i = 0; i < 8; i++)
                #pragma unroll
                for (int j = 0; j < 8; j++) acc[i][j] += a[i] * bb[j];
        }
        if (kt + 1 < KT) { G2_STORE(cur ^ 1); }
        __syncthreads();
    }

    float* Yb = g_Y + (size_t)b * N_ * C_;
    #pragma unroll
    for (int i = 0; i < 8; i++) {
        int n = n0 + ((i < 4) ? (ty * 4 + i) : (64 + ty * 4 + (i - 4)));
        float s = dv[n];
        float4 v0 = make_float4(acc[i][0]*s, acc[i][1]*s, acc[i][2]*s, acc[i][3]*s);
        float4 v1 = make_float4(acc[i][4]*s, acc[i][5]*s, acc[i][6]*s, acc[i][7]*s);
        *(float4*)(Yb + (size_t)n * C_ + tx * 4)      = v0;
        *(float4*)(Yb + (size_t)n * C_ + 64 + tx * 4) = v1;
    }
}

// ---------------- GEMM3 (linear): out[r,j] = sum_k Y[r,k]*Wt[k,j] + bias[j]
__global__ __launch_bounds__(256) void gemm3_kernel(const float* __restrict__ bias,
                                                    float* __restrict__ outp) {
    const int r0 = blockIdx.x * 128;   // flattened B*N rows

    __shared__ float As[2][16][132];
    __shared__ float Bs[2][16][128];

    const int tid = threadIdx.x;
    const int tx = tid & 15, ty = tid >> 4;

    float acc[8][8];
    #pragma unroll
    for (int i = 0; i < 8; i++)
        #pragma unroll
        for (int j = 0; j < 8; j++) acc[i][j] = 0.f;

    float4 ra[2], rb[2];

    #define G3_LOAD(k0)                                                          \
        _Pragma("unroll")                                                        \
        for (int i = 0; i < 2; i++) {                                            \
            int f = tid + i * 256;                                               \
            int m = f >> 2, q = f & 3;                                           \
            ra[i] = *(const float4*)(g_Y + (size_t)(r0 + m) * C_ + (k0) + q*4);  \
            int k = f >> 5, c = f & 31;                                          \
            rb[i] = *(const float4*)(g_Wt + (size_t)((k0) + k) * C_ + c * 4);    \
        }
    #define G3_STORE(buf)                                                        \
        _Pragma("unroll")                                                        \
        for (int i = 0; i < 2; i++) {                                            \
            int f = tid + i * 256;                                               \
            int m = f >> 2, q = f & 3;                                           \
            As[buf][q * 4 + 0][m] = ra[i].x;                                     \
            As[buf][q * 4 + 1][m] = ra[i].y;                                     \
            As[buf][q * 4 + 2][m] = ra[i].z;                                     \
            As[buf][q * 4 + 3][m] = ra[i].w;                                     \
            int k = f >> 5, c = f & 31;                                          \
            *(float4*)&Bs[buf][k][c * 4] = rb[i];                                \
        }

    G3_LOAD(0); G3_STORE(0); __syncthreads();
    const int KT = C_ / 16;  // 8
    for (int kt = 0; kt < KT; ++kt) {
        int cur = kt & 1;
        if (kt + 1 < KT) { G3_LOAD((kt + 1) * 16); }
        #pragma unroll
        for (int kk = 0; kk < 16; kk++) {
            float a[8], bb[8];
            *(float4*)&a[0]  = *(const float4*)&As[cur][kk][ty * 4];
            *(float4*)&a[4]  = *(const float4*)&As[cur][kk][64 + ty * 4];
            *(float4*)&bb[0] = *(const float4*)&Bs[cur][kk][tx * 4];
            *(float4*)&bb[4] = *(const float4*)&Bs[cur][kk][64 + tx * 4];
            #pragma unroll
            for (int i = 0; i < 8; i++)
                #pragma unroll
                for (int j = 0; j < 8; j++) acc[i][j] += a[i] * bb[j];
        }
        if (kt + 1 < KT) { G3_STORE(cur ^ 1); }
        __syncthreads();
    }

    float bi0[4], bi1[4];
    *(float4*)bi0 = *(const float4*)(bias + tx * 4);
    *(float4*)bi1 = *(const float4*)(bias + 64 + tx * 4);
    #pragma unroll
    for (int i = 0; i < 8; i++) {
        int r = r0 + ((i < 4) ? (ty * 4 + i) : (64 + ty * 4 + (i - 4)));
        float4 v0 = make_float4(acc[i][0]+bi0[0], acc[i][1]+bi0[1],
                                acc[i][2]+bi0[2], acc[i][3]+bi0[3]);
        float4 v1 = make_float4(acc[i][4]+bi1[0], acc[i][5]+bi1[1],
                                acc[i][6]+bi1[2], acc[i][7]+bi1[3]);
        *(float4*)(outp + (size_t)r * C_ + tx * 4)      = v0;
        *(float4*)(outp + (size_t)r * C_ + 64 + tx * 4) = v1;
    }
}

// ---------------- launch ----------------------------------------------------
extern "C" void kernel_launch(void* const* d_in, const int* in_sizes, int n_in,
                              void* d_out, int out_size) {
    // Identify inputs by element count (robust to metadata ordering):
    const float *x = nullptr, *H = nullptr, *W = nullptr, *bias = nullptr;
    for (int i = 0; i < n_in; i++) {
        long long s = in_sizes[i];
        if (s == (long long)B_ * N_ * E_)      H = (const float*)d_in[i];
        else if (s == (long long)B_ * N_ * C_) x = (const float*)d_in[i];
        else if (s == (long long)C_ * C_)      W = (const float*)d_in[i];
        else if (s == (long long)C_)           bias = (const float*)d_in[i];
    }
    float* outp = (float*)d_out;

    // degrees + weight transpose
    dv_kernel<<<B_ * N_ / 8, dim3(32, 8)>>>(H);
    de_part_kernel<<<dim3(E_ / 128, 8, B_), 128>>>(H);
    de_reduce_kernel<<<B_ * E_ / 256, 256>>>();
    wt_kernel<<<C_ * C_ / 256, 256>>>(W);

    // M = De^-1 H^T (Dv^-1/2 x)
    gemm1_kernel<<<dim3(E_ / 128, 1, B_), 256>>>(H, x);
    // Y = Dv^-1/2 (H M)
    gemm2_kernel<<<dim3(N_ / 128, 1, B_), 256>>>(H);
    // out = Y W^T + b
    gemm3_kernel<<<(B_ * N_) / 128, 256>>>(bias, outp);
}